// round 2
// baseline (speedup 1.0000x reference)
#include <cuda_runtime.h>
#include <math.h>

#define HDIM 128
#define MAXN 50000
#define MAXE 640000
#define TE   64      // edges / nodes per block
#define SP   260     // state row pitch in floats (K up to 257, 16B-aligned rows)
#define KC   16      // K-chunk staged into smem per step

// scatter-add destination + prepped edge data (static __device__ per harness rules)
__device__ float g_aggr[(size_t)MAXN * HDIM];
__device__ int   g_send[MAXE];
__device__ int   g_rec[MAXE];
__device__ float g_dist[MAXE];

__device__ __forceinline__ float silu_f(float v) {
    return v / (1.0f + expf(-v));
}

__global__ void zero_kernel(int n) {
    int i = blockIdx.x * blockDim.x + threadIdx.x;
    int st = gridDim.x * blockDim.x;
    for (; i < n; i += st) g_aggr[i] = 0.0f;
}

// ---------------------------------------------------------------------------
// Prep: decode edge_index (int32 OR int64 layout, detected on-device),
// clamp defensively, precompute per-edge distance.
// ---------------------------------------------------------------------------
__global__ void prep_kernel(const int* __restrict__ ei32,
                            const float* __restrict__ pos,
                            int N, int E) {
    // dtype detection: for int64 little-endian storage of values < 2^31,
    // every odd 32-bit word of the first elements is 0.
    bool is64 = true;
#pragma unroll
    for (int t = 0; t < 16; t++) is64 &= (ei32[2 * t + 1] == 0);

    int i = blockIdx.x * blockDim.x + threadIdx.x;
    int st = gridDim.x * blockDim.x;
    for (; i < E; i += st) {
        int s, r;
        if (is64) {
            s = ei32[2 * (size_t)i];
            r = ei32[2 * ((size_t)E + i)];
        } else {
            s = ei32[i];
            r = ei32[(size_t)E + i];
        }
        // defensive clamp (indices should already be in range)
        s = min(max(s, 0), N - 1);
        r = min(max(r, 0), N - 1);
        g_send[i] = s;
        g_rec[i]  = r;
        float dx = pos[s * 3 + 0] - pos[r * 3 + 0];
        float dy = pos[s * 3 + 1] - pos[r * 3 + 1];
        float dz = pos[s * 3 + 2] - pos[r * 3 + 2];
        g_dist[i] = sqrtf(dx * dx + dy * dy + dz * dz);
    }
}

// Register-blocked tile GEMM: acc[4][8] += sA[64 x K] * gw[K x 128]
// Thread tile: rows tr4..tr4+3, cols {tc4..tc4+3, 64+tc4..64+tc4+3}
template <int K>
__device__ __forceinline__ void tile_gemm(const float* __restrict__ gw,
                                          const float* sA, float* sW,
                                          int tr4, int tc4, int tid,
                                          float acc[4][8]) {
    for (int k0 = 0; k0 < K; k0 += KC) {
        __syncthreads();   // previous chunk consumers done / sA producers done
        for (int t = tid; t < KC * 32; t += 256) {
            int r = t >> 5;
            int c = (t & 31) * 4;
            *(float4*)&sW[r * 128 + c] =
                *(const float4*)&gw[(size_t)(k0 + r) * 128 + c];
        }
        __syncthreads();
#pragma unroll
        for (int kk = 0; kk < KC; kk++) {
            float a[4];
#pragma unroll
            for (int i = 0; i < 4; i++) a[i] = sA[(tr4 + i) * SP + k0 + kk];
            float4 wl = *(const float4*)&sW[kk * 128 + tc4];
            float4 wh = *(const float4*)&sW[kk * 128 + 64 + tc4];
            float w[8] = {wl.x, wl.y, wl.z, wl.w, wh.x, wh.y, wh.z, wh.w};
#pragma unroll
            for (int i = 0; i < 4; i++)
#pragma unroll
                for (int j = 0; j < 8; j++)
                    acc[i][j] = fmaf(a[i], w[j], acc[i][j]);
        }
    }
}

// ---------------------------------------------------------------------------
// Edge kernel: per 64-edge tile
//   state = [x[send], x[rec], dist]  (K = 257)
//   h = silu(state @ w1 + b1); msg = silu(h @ w2 + b2); atomicAdd into g_aggr
// ---------------------------------------------------------------------------
__global__ void __launch_bounds__(256) edge_kernel(
    const float* __restrict__ x,
    const float* __restrict__ w1, const float* __restrict__ b1,
    const float* __restrict__ w2, const float* __restrict__ b2,
    int N, int E) {
    extern __shared__ float sm[];
    float* sA  = sm;                 // TE*SP  (state, later reused for h)
    float* sW  = sA + TE * SP;       // KC*128
    float* sB1 = sW + KC * 128;      // 128
    float* sB2 = sB1 + 128;          // 128
    int* sSend = (int*)(sB2 + 128);  // TE
    int* sRec  = sSend + TE;         // TE

    const int tid = threadIdx.x;
    const int e0  = blockIdx.x * TE;

    if (tid < 128) { sB1[tid] = b1[tid]; sB2[tid] = b2[tid]; }
    if (tid < TE) {
        int ge = e0 + tid;
        int s = -1, r = -1;
        float d = 0.0f;
        if (ge < E) {
            s = g_send[ge];
            r = g_rec[ge];
            d = g_dist[ge];
        }
        sSend[tid] = s;
        sRec[tid]  = r;
        sA[tid * SP + 256] = d;
    }
    __syncthreads();

    // gather x[send] and x[rec] into state tile (float4, L2-resident x)
    const float4* x4 = (const float4*)x;
    for (int i = tid; i < TE * 32; i += 256) {
        int e = i >> 5;
        int f = i & 31;
        int s = sSend[e];
        float4 vs = make_float4(0.f, 0.f, 0.f, 0.f), vr = vs;
        if (s >= 0) {
            vs = x4[(size_t)s * 32 + f];
            vr = x4[(size_t)sRec[e] * 32 + f];
        }
        *(float4*)&sA[e * SP + f * 4]       = vs;
        *(float4*)&sA[e * SP + 128 + f * 4] = vr;
    }

    const int tr4 = (tid >> 4) * 4;
    const int tc4 = (tid & 15) * 4;

    float acc[4][8];
#pragma unroll
    for (int i = 0; i < 4; i++)
#pragma unroll
        for (int j = 0; j < 8; j++) acc[i][j] = 0.0f;

    // GEMM1 main K=256
    tile_gemm<256>(w1, sA, sW, tr4, tc4, tid, acc);

    // dist column (k = 256), weights straight from global (L2 hit)
    {
        float d[4];
#pragma unroll
        for (int i = 0; i < 4; i++) d[i] = sA[(tr4 + i) * SP + 256];
        float4 wl = *(const float4*)&w1[(size_t)256 * 128 + tc4];
        float4 wh = *(const float4*)&w1[(size_t)256 * 128 + 64 + tc4];
        float w[8] = {wl.x, wl.y, wl.z, wl.w, wh.x, wh.y, wh.z, wh.w};
#pragma unroll
        for (int i = 0; i < 4; i++)
#pragma unroll
            for (int j = 0; j < 8; j++)
                acc[i][j] = fmaf(d[i], w[j], acc[i][j]);
    }

    __syncthreads();  // all state reads done before overwriting sA with h

    // bias + SiLU, write h back into sA (cols 0..127 region)
#pragma unroll
    for (int i = 0; i < 4; i++) {
        float4 hl, hh;
        hl.x = silu_f(acc[i][0] + sB1[tc4 + 0]);
        hl.y = silu_f(acc[i][1] + sB1[tc4 + 1]);
        hl.z = silu_f(acc[i][2] + sB1[tc4 + 2]);
        hl.w = silu_f(acc[i][3] + sB1[tc4 + 3]);
        hh.x = silu_f(acc[i][4] + sB1[64 + tc4 + 0]);
        hh.y = silu_f(acc[i][5] + sB1[64 + tc4 + 1]);
        hh.z = silu_f(acc[i][6] + sB1[64 + tc4 + 2]);
        hh.w = silu_f(acc[i][7] + sB1[64 + tc4 + 3]);
        *(float4*)&sA[(tr4 + i) * SP + tc4]      = hl;
        *(float4*)&sA[(tr4 + i) * SP + 64 + tc4] = hh;
    }

#pragma unroll
    for (int i = 0; i < 4; i++)
#pragma unroll
        for (int j = 0; j < 8; j++) acc[i][j] = 0.0f;

    // GEMM2 K=128 (leading sync inside tile_gemm orders the h stores)
    tile_gemm<128>(w2, sA, sW, tr4, tc4, tid, acc);

    // bias + SiLU + scatter-add
#pragma unroll
    for (int i = 0; i < 4; i++) {
        int r = sRec[tr4 + i];
        if (r < 0) continue;
        float* dst = &g_aggr[(size_t)r * 128];
#pragma unroll
        for (int j = 0; j < 4; j++)
            atomicAdd(dst + tc4 + j, silu_f(acc[i][j] + sB2[tc4 + j]));
#pragma unroll
        for (int j = 0; j < 4; j++)
            atomicAdd(dst + 64 + tc4 + j,
                      silu_f(acc[i][4 + j] + sB2[64 + tc4 + j]));
    }
}

// ---------------------------------------------------------------------------
// Node kernel: u = silu([x, aggr] @ uw1 + ub1); out = u @ uw2 + ub2
// ---------------------------------------------------------------------------
__global__ void __launch_bounds__(256) node_kernel(
    const float* __restrict__ x,
    const float* __restrict__ w1, const float* __restrict__ b1,
    const float* __restrict__ w2, const float* __restrict__ b2,
    float* __restrict__ out, int N) {
    extern __shared__ float sm[];
    float* sA  = sm;
    float* sW  = sA + TE * SP;
    float* sB1 = sW + KC * 128;
    float* sB2 = sB1 + 128;

    const int tid = threadIdx.x;
    const int n0  = blockIdx.x * TE;

    if (tid < 128) { sB1[tid] = b1[tid]; sB2[tid] = b2[tid]; }

    const float4* x4 = (const float4*)x;
    const float4* a4 = (const float4*)g_aggr;
    for (int i = tid; i < TE * 32; i += 256) {
        int e = i >> 5;
        int f = i & 31;
        int gn = n0 + e;
        float4 vx = make_float4(0.f, 0.f, 0.f, 0.f), va = vx;
        if (gn < N) {
            vx = x4[(size_t)gn * 32 + f];
            va = a4[(size_t)gn * 32 + f];
        }
        *(float4*)&sA[e * SP + f * 4]       = vx;
        *(float4*)&sA[e * SP + 128 + f * 4] = va;
    }

    const int tr4 = (tid >> 4) * 4;
    const int tc4 = (tid & 15) * 4;

    float acc[4][8];
#pragma unroll
    for (int i = 0; i < 4; i++)
#pragma unroll
        for (int j = 0; j < 8; j++) acc[i][j] = 0.0f;

    tile_gemm<256>(w1, sA, sW, tr4, tc4, tid, acc);

    __syncthreads();
#pragma unroll
    for (int i = 0; i < 4; i++) {
        float4 hl, hh;
        hl.x = silu_f(acc[i][0] + sB1[tc4 + 0]);
        hl.y = silu_f(acc[i][1] + sB1[tc4 + 1]);
        hl.z = silu_f(acc[i][2] + sB1[tc4 + 2]);
        hl.w = silu_f(acc[i][3] + sB1[tc4 + 3]);
        hh.x = silu_f(acc[i][4] + sB1[64 + tc4 + 0]);
        hh.y = silu_f(acc[i][5] + sB1[64 + tc4 + 1]);
        hh.z = silu_f(acc[i][6] + sB1[64 + tc4 + 2]);
        hh.w = silu_f(acc[i][7] + sB1[64 + tc4 + 3]);
        *(float4*)&sA[(tr4 + i) * SP + tc4]      = hl;
        *(float4*)&sA[(tr4 + i) * SP + 64 + tc4] = hh;
    }

#pragma unroll
    for (int i = 0; i < 4; i++)
#pragma unroll
        for (int j = 0; j < 8; j++) acc[i][j] = 0.0f;

    tile_gemm<128>(w2, sA, sW, tr4, tc4, tid, acc);

    // bias (no SiLU on final layer) + store
#pragma unroll
    for (int i = 0; i < 4; i++) {
        int gn = n0 + tr4 + i;
        if (gn >= N) continue;
        float4 ol, oh;
        ol.x = acc[i][0] + sB2[tc4 + 0];
        ol.y = acc[i][1] + sB2[tc4 + 1];
        ol.z = acc[i][2] + sB2[tc4 + 2];
        ol.w = acc[i][3] + sB2[tc4 + 3];
        oh.x = acc[i][4] + sB2[64 + tc4 + 0];
        oh.y = acc[i][5] + sB2[64 + tc4 + 1];
        oh.z = acc[i][6] + sB2[64 + tc4 + 2];
        oh.w = acc[i][7] + sB2[64 + tc4 + 3];
        *(float4*)&out[(size_t)gn * 128 + tc4]      = ol;
        *(float4*)&out[(size_t)gn * 128 + 64 + tc4] = oh;
    }
}

extern "C" void kernel_launch(void* const* d_in, const int* in_sizes, int n_in,
                              void* d_out, int out_size) {
    const float* x    = (const float*)d_in[0];
    const float* pos  = (const float*)d_in[1];
    const int*   ei   = (const int*)d_in[2];   // int32 OR int64 words — detected on device
    const float* mw1  = (const float*)d_in[3];
    const float* mb1  = (const float*)d_in[4];
    const float* mw2  = (const float*)d_in[5];
    const float* mb2  = (const float*)d_in[6];
    const float* uw1  = (const float*)d_in[7];
    const float* ub1  = (const float*)d_in[8];
    const float* uw2  = (const float*)d_in[9];
    const float* ub2  = (const float*)d_in[10];

    int N = in_sizes[0] / HDIM;
    int E = in_sizes[2] / 2;

    // smem: state 64*260 + wchunk 16*128 + 2 biases + 2*64 ints
    const int SMEM_BYTES =
        (TE * SP + KC * 128 + 256) * (int)sizeof(float) + 2 * TE * (int)sizeof(int);

    cudaFuncSetAttribute(edge_kernel, cudaFuncAttributeMaxDynamicSharedMemorySize,
                         SMEM_BYTES);
    cudaFuncSetAttribute(node_kernel, cudaFuncAttributeMaxDynamicSharedMemorySize,
                         SMEM_BYTES);

    zero_kernel<<<256, 256>>>(N * HDIM);
    prep_kernel<<<512, 256>>>(ei, pos, N, E);
    edge_kernel<<<(E + TE - 1) / TE, 256, SMEM_BYTES>>>(
        x, mw1, mb1, mw2, mb2, N, E);
    node_kernel<<<(N + TE - 1) / TE, 256, SMEM_BYTES>>>(
        x, uw1, ub1, uw2, ub2, (float*)d_out, N);
}

// round 4
// speedup vs baseline: 2.1803x; 2.1803x over previous
#include <cuda_runtime.h>
#include <math.h>
#include <stdint.h>

#define HDIM 128
#define MAXN 50000
#define MAXE 640000
#define TM   128

// shared layout (floats)
#define SA_ST  260
#define WB_ST  36
#define WB_F   (128 * SA_ST)          // 33280
#define WB_SZ  (128 * WB_ST)          // 4608
#define B1_F   (WB_F + 2 * WB_SZ)     // 42496
#define B2_F   (B1_F + 128)
#define W1L_F  (B2_F + 128)
#define DIST_F (W1L_F + 128)
#define REC_F  (DIST_F + 128)
#define SEND_F (REC_F + 128)
#define SMEM_FLOATS (SEND_F + 128)
#define SMEM_BYTES  (SMEM_FLOATS * 4)   // 173056

// ------------------------- device scratch -------------------------
__device__ __align__(16) float g_aggr[(size_t)MAXN * HDIM];
__device__ int   g_send[MAXE];
__device__ int   g_rec[MAXE];
__device__ float g_dist[MAXE];
__device__ __align__(16) float g_w1t[128 * 256];  // tf32-rounded bits, [n][k]
__device__ __align__(16) float g_w2t[128 * 128];  // tf32-rounded bits, [n][k]

// ------------------------- helpers -------------------------
__device__ __forceinline__ float silu_f(float v) {
    return __fdividef(v, 1.0f + __expf(-v));
}
__device__ __forceinline__ uint32_t tf32r(float f) {
    uint32_t r;
    asm("cvt.rna.tf32.f32 %0, %1;" : "=r"(r) : "f"(f));
    return r;
}
__device__ __forceinline__ void mma8(float d[4], const uint32_t a[4],
                                     const uint32_t b[2]) {
    asm volatile(
        "mma.sync.aligned.m16n8k8.row.col.f32.tf32.tf32.f32 "
        "{%0,%1,%2,%3},{%4,%5,%6,%7},{%8,%9},{%0,%1,%2,%3};"
        : "+f"(d[0]), "+f"(d[1]), "+f"(d[2]), "+f"(d[3])
        : "r"(a[0]), "r"(a[1]), "r"(a[2]), "r"(a[3]), "r"(b[0]), "r"(b[1]));
}
__device__ __forceinline__ void red4(float* p, float a, float b, float c, float d) {
    asm volatile("red.global.add.v4.f32 [%0], {%1,%2,%3,%4};"
                 :: "l"(p), "f"(a), "f"(b), "f"(c), "f"(d) : "memory");
}

// ------------------------- prep kernels -------------------------
__global__ void zero_kernel(int n) {
    int i = blockIdx.x * blockDim.x + threadIdx.x;
    int st = gridDim.x * blockDim.x;
    for (; i < n; i += st) g_aggr[i] = 0.0f;
}

__global__ void prep_kernel(const int* __restrict__ ei32,
                            const float* __restrict__ pos, int N, int E) {
    bool is64 = true;
#pragma unroll
    for (int t = 0; t < 16; t++) is64 &= (ei32[2 * t + 1] == 0);
    int i = blockIdx.x * blockDim.x + threadIdx.x;
    int st = gridDim.x * blockDim.x;
    for (; i < E; i += st) {
        int s, r;
        if (is64) { s = ei32[2 * (size_t)i]; r = ei32[2 * ((size_t)E + i)]; }
        else      { s = ei32[i];             r = ei32[(size_t)E + i]; }
        s = min(max(s, 0), N - 1);
        r = min(max(r, 0), N - 1);
        g_send[i] = s;
        g_rec[i]  = r;
        float dx = pos[s * 3 + 0] - pos[r * 3 + 0];
        float dy = pos[s * 3 + 1] - pos[r * 3 + 1];
        float dz = pos[s * 3 + 2] - pos[r * 3 + 2];
        g_dist[i] = sqrtf(dx * dx + dy * dy + dz * dz);
    }
}

// transpose weights to [n][k] and pre-round to tf32
__global__ void wt_kernel(const float* __restrict__ w1, const float* __restrict__ w2) {
    int i = blockIdx.x * blockDim.x + threadIdx.x;
    int st = gridDim.x * blockDim.x;
    for (; i < 128 * 256 + 128 * 128; i += st) {
        if (i < 128 * 256) {
            int n = i >> 8, k = i & 255;
            g_w1t[i] = __uint_as_float(tf32r(w1[k * 128 + n]));
        } else {
            int j = i - 128 * 256;
            int n = j >> 7, k = j & 127;
            g_w2t[j] = __uint_as_float(tf32r(w2[k * 128 + n]));
        }
    }
}

// ------------------------- tiled tf32 mma GEMM -------------------------
// acc[mf][nf][reg] += A_tile(128 x nCh*32, in sA cols 0..) * Bt(gB: [128][Kst])^T
__device__ __forceinline__ void gemm_tc(const float* __restrict__ gB, int Kst,
                                        int nCh, float* sm, int mh, int nq,
                                        int lane, int tid, float acc[4][4][4]) {
    uint4 pf[4];
#pragma unroll
    for (int it = 0; it < 4; it++) {
        int idx = tid + it * 256;
        int n = idx >> 3, k4 = idx & 7;
        pf[it] = *(const uint4*)(gB + (size_t)n * Kst + k4 * 4);
    }
    for (int c = 0; c < nCh; c++) {
        float* wb = sm + WB_F + (c & 1) * WB_SZ;
#pragma unroll
        for (int it = 0; it < 4; it++) {
            int idx = tid + it * 256;
            int n = idx >> 3, k4 = idx & 7;
            *(uint4*)&wb[n * WB_ST + k4 * 4] = pf[it];
        }
        __syncthreads();
        if (c + 1 < nCh) {
#pragma unroll
            for (int it = 0; it < 4; it++) {
                int idx = tid + it * 256;
                int n = idx >> 3, k4 = idx & 7;
                pf[it] = *(const uint4*)(gB + (size_t)n * Kst + (c + 1) * 32 + k4 * 4);
            }
        }
        const uint32_t* sAu = (const uint32_t*)sm;
        const uint32_t* wbu = (const uint32_t*)wb;
#pragma unroll
        for (int kk = 0; kk < 32; kk += 8) {
            int kc = c * 32 + kk + (lane & 3);
            uint32_t a[4][4], b[4][2];
#pragma unroll
            for (int mf = 0; mf < 4; mf++) {
                int r = mh * 64 + mf * 16 + (lane >> 2);
                a[mf][0] = sAu[r * SA_ST + kc];
                a[mf][1] = sAu[(r + 8) * SA_ST + kc];
                a[mf][2] = sAu[r * SA_ST + kc + 4];
                a[mf][3] = sAu[(r + 8) * SA_ST + kc + 4];
            }
#pragma unroll
            for (int nf = 0; nf < 4; nf++) {
                int n = nq * 32 + nf * 8 + (lane >> 2);
                b[nf][0] = wbu[n * WB_ST + kk + (lane & 3)];
                b[nf][1] = wbu[n * WB_ST + kk + (lane & 3) + 4];
            }
#pragma unroll
            for (int mf = 0; mf < 4; mf++)
#pragma unroll
                for (int nf = 0; nf < 4; nf++)
                    mma8(acc[mf][nf], a[mf], b[nf]);
        }
    }
    __syncthreads();  // all A/B reads done before caller mutates sA
}

// ------------------------- fused MLP kernel (edge / node) -------------------------
template <bool EDGE>
__global__ void __launch_bounds__(256, 1) mlp_mma_kernel(
    const float* __restrict__ x,
    const float* __restrict__ w1full,   // original w1 (dist row, edge only)
    const float* __restrict__ b1, const float* __restrict__ b2,
    float* __restrict__ out, int M) {
    extern __shared__ float sm[];
    const int tid  = threadIdx.x;
    const int lane = tid & 31;
    const int wid  = tid >> 5;
    const int mh   = wid >> 2;   // 0..1  (M half)
    const int nq   = wid & 3;    // 0..3  (N quarter)
    const int m0   = blockIdx.x * TM;

    if (tid < 128) {
        sm[B1_F + tid] = b1[tid];
        sm[B2_F + tid] = b2[tid];
        if (EDGE) {
            sm[W1L_F + tid] = w1full[(size_t)256 * 128 + tid];
            int ge = m0 + tid;
            if (ge < M) {
                ((int*)sm)[SEND_F + tid] = g_send[ge];
                ((int*)sm)[REC_F + tid]  = g_rec[ge];
                sm[DIST_F + tid]         = g_dist[ge];
            } else {
                ((int*)sm)[SEND_F + tid] = 0;
                ((int*)sm)[REC_F + tid]  = -1;
                sm[DIST_F + tid]         = 0.0f;
            }
        }
    }
    __syncthreads();

    // gather state rows (tf32-rounded): cols 0..127 / 128..255
    const float4* x4 = (const float4*)x;
    const float4* a4 = (const float4*)g_aggr;
    for (int i = tid; i < TM * 32; i += 256) {
        int r = i >> 5, f = i & 31;
        float4 v0, v1;
        if (EDGE) {
            int s  = ((int*)sm)[SEND_F + r];
            int rc = ((int*)sm)[REC_F + r];
            if (rc < 0) rc = 0;
            v0 = x4[(size_t)s * 32 + f];
            v1 = x4[(size_t)rc * 32 + f];
        } else {
            int gn = m0 + r;
            if (gn >= M) gn = M - 1;
            v0 = x4[(size_t)gn * 32 + f];
            v1 = a4[(size_t)gn * 32 + f];
        }
        uint4 u0, u1;
        u0.x = tf32r(v0.x); u0.y = tf32r(v0.y); u0.z = tf32r(v0.z); u0.w = tf32r(v0.w);
        u1.x = tf32r(v1.x); u1.y = tf32r(v1.y); u1.z = tf32r(v1.z); u1.w = tf32r(v1.w);
        *(uint4*)&sm[r * SA_ST + f * 4]       = u0;
        *(uint4*)&sm[r * SA_ST + 128 + f * 4] = u1;
    }
    // (first gemm chunk's store+sync orders the gather for all warps)

    float acc[4][4][4];
#pragma unroll
    for (int mf = 0; mf < 4; mf++)
#pragma unroll
        for (int nf = 0; nf < 4; nf++)
#pragma unroll
            for (int g = 0; g < 4; g++) acc[mf][nf][g] = 0.0f;

    // GEMM1: K=256
    gemm_tc(g_w1t, 256, 8, sm, mh, nq, lane, tid, acc);

    // epilogue 1: h = silu(acc + b1 [+ dist*w1_last]) -> tf32 -> sA cols 0..127
#pragma unroll
    for (int mf = 0; mf < 4; mf++) {
        int r0 = mh * 64 + mf * 16 + (lane >> 2);
        int r1 = r0 + 8;
        float d0 = EDGE ? sm[DIST_F + r0] : 0.0f;
        float d1 = EDGE ? sm[DIST_F + r1] : 0.0f;
#pragma unroll
        for (int nf = 0; nf < 4; nf++) {
            int c0 = nq * 32 + nf * 8 + (lane & 3) * 2;
            float* v = acc[mf][nf];
            float wl0 = EDGE ? sm[W1L_F + c0] : 0.0f;
            float wl1 = EDGE ? sm[W1L_F + c0 + 1] : 0.0f;
            uint32_t h00 = tf32r(silu_f(v[0] + sm[B1_F + c0]     + d0 * wl0));
            uint32_t h01 = tf32r(silu_f(v[1] + sm[B1_F + c0 + 1] + d0 * wl1));
            uint32_t h10 = tf32r(silu_f(v[2] + sm[B1_F + c0]     + d1 * wl0));
            uint32_t h11 = tf32r(silu_f(v[3] + sm[B1_F + c0 + 1] + d1 * wl1));
            ((uint32_t*)sm)[r0 * SA_ST + c0]     = h00;
            ((uint32_t*)sm)[r0 * SA_ST + c0 + 1] = h01;
            ((uint32_t*)sm)[r1 * SA_ST + c0]     = h10;
            ((uint32_t*)sm)[r1 * SA_ST + c0 + 1] = h11;
            v[0] = v[1] = v[2] = v[3] = 0.0f;
        }
    }
    // (first GEMM2 chunk's sync orders these writes)

    // GEMM2: K=128
    gemm_tc(g_w2t, 128, 4, sm, mh, nq, lane, tid, acc);

    // epilogue 2: stage result (fp32) into sA cols 128..255
#pragma unroll
    for (int mf = 0; mf < 4; mf++) {
        int r0 = mh * 64 + mf * 16 + (lane >> 2);
        int r1 = r0 + 8;
#pragma unroll
        for (int nf = 0; nf < 4; nf++) {
            int c0 = nq * 32 + nf * 8 + (lane & 3) * 2;
            float* v = acc[mf][nf];
            float o00 = v[0] + sm[B2_F + c0];
            float o01 = v[1] + sm[B2_F + c0 + 1];
            float o10 = v[2] + sm[B2_F + c0];
            float o11 = v[3] + sm[B2_F + c0 + 1];
            if (EDGE) {
                o00 = silu_f(o00); o01 = silu_f(o01);
                o10 = silu_f(o10); o11 = silu_f(o11);
            }
            sm[r0 * SA_ST + 128 + c0]     = o00;
            sm[r0 * SA_ST + 128 + c0 + 1] = o01;
            sm[r1 * SA_ST + 128 + c0]     = o10;
            sm[r1 * SA_ST + 128 + c0 + 1] = o11;
        }
    }
    __syncthreads();

    // writeout: row-coalesced scatter-add (edge) or store (node)
    {
        int r = tid >> 1, half = tid & 1;
        const float4* src = (const float4*)&sm[r * SA_ST + 128 + half * 64];
        if (EDGE) {
            int rc = ((int*)sm)[REC_F + r];
            if (rc >= 0) {
                float* dst = &g_aggr[(size_t)rc * HDIM + half * 64];
#pragma unroll
                for (int j = 0; j < 16; j++) {
                    float4 v = src[j];
                    red4(dst + j * 4, v.x, v.y, v.z, v.w);
                }
            }
        } else {
            int gn = m0 + r;
            if (gn < M) {
                float4* dst = (float4*)&out[(size_t)gn * HDIM + half * 64];
#pragma unroll
                for (int j = 0; j < 16; j++) dst[j] = src[j];
            }
        }
    }
}

// ------------------------- launch -------------------------
extern "C" void kernel_launch(void* const* d_in, const int* in_sizes, int n_in,
                              void* d_out, int out_size) {
    const float* x   = (const float*)d_in[0];
    const float* pos = (const float*)d_in[1];
    const int*   ei  = (const int*)d_in[2];
    const float* mw1 = (const float*)d_in[3];
    const float* mb1 = (const float*)d_in[4];
    const float* mw2 = (const float*)d_in[5];
    const float* mb2 = (const float*)d_in[6];
    const float* uw1 = (const float*)d_in[7];
    const float* ub1 = (const float*)d_in[8];
    const float* uw2 = (const float*)d_in[9];
    const float* ub2 = (const float*)d_in[10];

    int N = in_sizes[0] / HDIM;
    int E = in_sizes[2] / 2;

    cudaFuncSetAttribute(mlp_mma_kernel<true>,
                         cudaFuncAttributeMaxDynamicSharedMemorySize, SMEM_BYTES);
    cudaFuncSetAttribute(mlp_mma_kernel<false>,
                         cudaFuncAttributeMaxDynamicSharedMemorySize, SMEM_BYTES);

    zero_kernel<<<256, 256>>>(N * HDIM);
    prep_kernel<<<512, 256>>>(ei, pos, N, E);
    // edge weights first; node weights transposed after (separate launch reuses kernel)
    wt_kernel<<<192, 256>>>(mw1, mw2);
    mlp_mma_kernel<true><<<(E + TM - 1) / TM, 256, SMEM_BYTES>>>(
        x, mw1, mb1, mb2, nullptr, E);
    wt_kernel<<<192, 256>>>(uw1, uw2);
    mlp_mma_kernel<false><<<(N + TM - 1) / TM, 256, SMEM_BYTES>>>(
        x, uw1, ub1, ub2, (float*)d_out, N);
}

// round 5
// speedup vs baseline: 2.3139x; 1.0613x over previous
#include <cuda_runtime.h>
#include <math.h>
#include <stdint.h>

#define HDIM 128
#define MAXN 50000
#define MAXE 640000
#define TM   64

// shared layout (floats)
#define SA_ST  260
#define WB_ST  36
#define WB_F   (TM * SA_ST)           // 16640
#define WB_SZ  (128 * WB_ST)          // 4608
#define B1_F   (WB_F + 2 * WB_SZ)
#define B2_F   (B1_F + 128)
#define W1L_F  (B2_F + 128)
#define DIST_F (W1L_F + 128)
#define REC_F  (DIST_F + TM)
#define SEND_F (REC_F + TM)
#define SMEM_FLOATS (SEND_F + TM)
#define SMEM_BYTES  (SMEM_FLOATS * 4)   // ~105.7 KB

// ------------------------- device scratch -------------------------
__device__ __align__(16) float g_aggr[(size_t)MAXN * HDIM];
__device__ int   g_send[MAXE];
__device__ int   g_rec[MAXE];
__device__ float g_dist[MAXE];
__device__ __align__(16) float g_w1t[128 * 256];  // tf32-rounded, [n][k]
__device__ __align__(16) float g_w2t[128 * 128];  // tf32-rounded, [n][k]

// ------------------------- helpers -------------------------
__device__ __forceinline__ float silu_f(float v) {
    return __fdividef(v, 1.0f + __expf(-v));
}
__device__ __forceinline__ uint32_t tf32r(float f) {
    uint32_t r;
    asm("cvt.rna.tf32.f32 %0, %1;" : "=r"(r) : "f"(f));
    return r;
}
__device__ __forceinline__ void mma8(float d[4], const uint32_t a[4],
                                     const uint32_t b[2]) {
    asm volatile(
        "mma.sync.aligned.m16n8k8.row.col.f32.tf32.tf32.f32 "
        "{%0,%1,%2,%3},{%4,%5,%6,%7},{%8,%9},{%0,%1,%2,%3};"
        : "+f"(d[0]), "+f"(d[1]), "+f"(d[2]), "+f"(d[3])
        : "r"(a[0]), "r"(a[1]), "r"(a[2]), "r"(a[3]), "r"(b[0]), "r"(b[1]));
}
__device__ __forceinline__ void red4(float* p, float a, float b, float c, float d) {
    asm volatile("red.global.add.v4.f32 [%0], {%1,%2,%3,%4};"
                 :: "l"(p), "f"(a), "f"(b), "f"(c), "f"(d) : "memory");
}

// ------------------------- prep kernels -------------------------
__global__ void zero_kernel(int n) {
    int i = blockIdx.x * blockDim.x + threadIdx.x;
    int st = gridDim.x * blockDim.x;
    for (; i < n; i += st) g_aggr[i] = 0.0f;
}

__global__ void prep_kernel(const int* __restrict__ ei32,
                            const float* __restrict__ pos, int N, int E) {
    bool is64 = true;
#pragma unroll
    for (int t = 0; t < 16; t++) is64 &= (ei32[2 * t + 1] == 0);
    int i = blockIdx.x * blockDim.x + threadIdx.x;
    int st = gridDim.x * blockDim.x;
    for (; i < E; i += st) {
        int s, r;
        if (is64) { s = ei32[2 * (size_t)i]; r = ei32[2 * ((size_t)E + i)]; }
        else      { s = ei32[i];             r = ei32[(size_t)E + i]; }
        s = min(max(s, 0), N - 1);
        r = min(max(r, 0), N - 1);
        g_send[i] = s;
        g_rec[i]  = r;
        float dx = pos[s * 3 + 0] - pos[r * 3 + 0];
        float dy = pos[s * 3 + 1] - pos[r * 3 + 1];
        float dz = pos[s * 3 + 2] - pos[r * 3 + 2];
        g_dist[i] = sqrtf(dx * dx + dy * dy + dz * dz);
    }
}

// transpose weights to [n][k] and pre-round to tf32
__global__ void wt_kernel(const float* __restrict__ w1, const float* __restrict__ w2) {
    int i = blockIdx.x * blockDim.x + threadIdx.x;
    int st = gridDim.x * blockDim.x;
    for (; i < 128 * 256 + 128 * 128; i += st) {
        if (i < 128 * 256) {
            int n = i >> 8, k = i & 255;
            g_w1t[i] = __uint_as_float(tf32r(w1[k * 128 + n]));
        } else {
            int j = i - 128 * 256;
            int n = j >> 7, k = j & 127;
            g_w2t[j] = __uint_as_float(tf32r(w2[k * 128 + n]));
        }
    }
}

// ------------------------- tiled tf32 mma GEMM -------------------------
// acc[mf][nf][reg] += A_tile(64 x nCh*32, in sA cols 0..) * Bt(gB: [128][Kst])^T
__device__ __forceinline__ void gemm_tc(const float* __restrict__ gB, int Kst,
                                        int nCh, float* sm, int mh, int nq,
                                        int lane, int tid, float acc[2][4][4]) {
    uint4 pf[4];
#pragma unroll
    for (int it = 0; it < 4; it++) {
        int idx = tid + it * 256;
        int n = idx >> 3, k4 = idx & 7;
        pf[it] = *(const uint4*)(gB + (size_t)n * Kst + k4 * 4);
    }
    for (int c = 0; c < nCh; c++) {
        float* wb = sm + WB_F + (c & 1) * WB_SZ;
#pragma unroll
        for (int it = 0; it < 4; it++) {
            int idx = tid + it * 256;
            int n = idx >> 3, k4 = idx & 7;
            *(uint4*)&wb[n * WB_ST + k4 * 4] = pf[it];
        }
        __syncthreads();
        if (c + 1 < nCh) {
#pragma unroll
            for (int it = 0; it < 4; it++) {
                int idx = tid + it * 256;
                int n = idx >> 3, k4 = idx & 7;
                pf[it] = *(const uint4*)(gB + (size_t)n * Kst + (c + 1) * 32 + k4 * 4);
            }
        }
        const uint32_t* sAu = (const uint32_t*)sm;
        const uint32_t* wbu = (const uint32_t*)wb;
#pragma unroll
        for (int kk = 0; kk < 32; kk += 8) {
            int kc = c * 32 + kk + (lane & 3);
            uint32_t a[2][4], b[4][2];
#pragma unroll
            for (int mf = 0; mf < 2; mf++) {
                int r = mh * 32 + mf * 16 + (lane >> 2);
                a[mf][0] = sAu[r * SA_ST + kc];
                a[mf][1] = sAu[(r + 8) * SA_ST + kc];
                a[mf][2] = sAu[r * SA_ST + kc + 4];
                a[mf][3] = sAu[(r + 8) * SA_ST + kc + 4];
            }
#pragma unroll
            for (int nf = 0; nf < 4; nf++) {
                int n = nq * 32 + nf * 8 + (lane >> 2);
                b[nf][0] = wbu[n * WB_ST + kk + (lane & 3)];
                b[nf][1] = wbu[n * WB_ST + kk + (lane & 3) + 4];
            }
#pragma unroll
            for (int mf = 0; mf < 2; mf++)
#pragma unroll
                for (int nf = 0; nf < 4; nf++)
                    mma8(acc[mf][nf], a[mf], b[nf]);
        }
    }
    __syncthreads();  // all A/B reads done before caller mutates sA
}

// ------------------------- fused MLP kernel (edge / node) -------------------------
template <bool EDGE>
__global__ void __launch_bounds__(256, 2) mlp_mma_kernel(
    const float* __restrict__ x,
    const float* __restrict__ w1full,   // original w1 (dist row, edge only)
    const float* __restrict__ b1, const float* __restrict__ b2,
    float* __restrict__ out, int M) {
    extern __shared__ float sm[];
    const int tid  = threadIdx.x;
    const int lane = tid & 31;
    const int wid  = tid >> 5;
    const int mh   = wid >> 2;   // 0..1  (M half: 32 rows)
    const int nq   = wid & 3;    // 0..3  (N quarter)
    const int m0   = blockIdx.x * TM;

    if (tid < 128) {
        sm[B1_F + tid] = b1[tid];
        sm[B2_F + tid] = b2[tid];
        if (EDGE) sm[W1L_F + tid] = w1full[(size_t)256 * 128 + tid];
    }
    if (EDGE && tid < TM) {
        int ge = m0 + tid;
        if (ge < M) {
            ((int*)sm)[SEND_F + tid] = g_send[ge];
            ((int*)sm)[REC_F + tid]  = g_rec[ge];
            sm[DIST_F + tid]         = g_dist[ge];
        } else {
            ((int*)sm)[SEND_F + tid] = 0;
            ((int*)sm)[REC_F + tid]  = -1;
            sm[DIST_F + tid]         = 0.0f;
        }
    }
    __syncthreads();

    // gather state rows (tf32-rounded): cols 0..127 / 128..255
    const float4* x4 = (const float4*)x;
    const float4* a4 = (const float4*)g_aggr;
    for (int i = tid; i < TM * 32; i += 256) {
        int r = i >> 5, f = i & 31;
        float4 v0, v1;
        if (EDGE) {
            int s  = ((int*)sm)[SEND_F + r];
            int rc = ((int*)sm)[REC_F + r];
            if (rc < 0) rc = 0;
            v0 = x4[(size_t)s * 32 + f];
            v1 = x4[(size_t)rc * 32 + f];
        } else {
            int gn = m0 + r;
            if (gn >= M) gn = M - 1;
            v0 = x4[(size_t)gn * 32 + f];
            v1 = a4[(size_t)gn * 32 + f];
        }
        uint4 u0, u1;
        u0.x = tf32r(v0.x); u0.y = tf32r(v0.y); u0.z = tf32r(v0.z); u0.w = tf32r(v0.w);
        u1.x = tf32r(v1.x); u1.y = tf32r(v1.y); u1.z = tf32r(v1.z); u1.w = tf32r(v1.w);
        *(uint4*)&sm[r * SA_ST + f * 4]       = u0;
        *(uint4*)&sm[r * SA_ST + 128 + f * 4] = u1;
    }
    // (first gemm chunk's store+sync orders the gather for all warps)

    float acc[2][4][4];
#pragma unroll
    for (int mf = 0; mf < 2; mf++)
#pragma unroll
        for (int nf = 0; nf < 4; nf++)
#pragma unroll
            for (int g = 0; g < 4; g++) acc[mf][nf][g] = 0.0f;

    // GEMM1: K=256
    gemm_tc(g_w1t, 256, 8, sm, mh, nq, lane, tid, acc);

    // epilogue 1: h = silu(acc + b1 [+ dist*w1_last]) -> tf32 -> sA cols 0..127
#pragma unroll
    for (int mf = 0; mf < 2; mf++) {
        int r0 = mh * 32 + mf * 16 + (lane >> 2);
        int r1 = r0 + 8;
        float d0 = EDGE ? sm[DIST_F + r0] : 0.0f;
        float d1 = EDGE ? sm[DIST_F + r1] : 0.0f;
#pragma unroll
        for (int nf = 0; nf < 4; nf++) {
            int c0 = nq * 32 + nf * 8 + (lane & 3) * 2;
            float* v = acc[mf][nf];
            float wl0 = EDGE ? sm[W1L_F + c0] : 0.0f;
            float wl1 = EDGE ? sm[W1L_F + c0 + 1] : 0.0f;
            uint32_t h00 = tf32r(silu_f(v[0] + sm[B1_F + c0]     + d0 * wl0));
            uint32_t h01 = tf32r(silu_f(v[1] + sm[B1_F + c0 + 1] + d0 * wl1));
            uint32_t h10 = tf32r(silu_f(v[2] + sm[B1_F + c0]     + d1 * wl0));
            uint32_t h11 = tf32r(silu_f(v[3] + sm[B1_F + c0 + 1] + d1 * wl1));
            ((uint32_t*)sm)[r0 * SA_ST + c0]     = h00;
            ((uint32_t*)sm)[r0 * SA_ST + c0 + 1] = h01;
            ((uint32_t*)sm)[r1 * SA_ST + c0]     = h10;
            ((uint32_t*)sm)[r1 * SA_ST + c0 + 1] = h11;
            v[0] = v[1] = v[2] = v[3] = 0.0f;
        }
    }
    // (first GEMM2 chunk's sync orders these writes)

    // GEMM2: K=128
    gemm_tc(g_w2t, 128, 4, sm, mh, nq, lane, tid, acc);

    // epilogue 2: stage result (fp32) into sA cols 128..255
#pragma unroll
    for (int mf = 0; mf < 2; mf++) {
        int r0 = mh * 32 + mf * 16 + (lane >> 2);
        int r1 = r0 + 8;
#pragma unroll
        for (int nf = 0; nf < 4; nf++) {
            int c0 = nq * 32 + nf * 8 + (lane & 3) * 2;
            float* v = acc[mf][nf];
            float o00 = v[0] + sm[B2_F + c0];
            float o01 = v[1] + sm[B2_F + c0 + 1];
            float o10 = v[2] + sm[B2_F + c0];
            float o11 = v[3] + sm[B2_F + c0 + 1];
            if (EDGE) {
                o00 = silu_f(o00); o01 = silu_f(o01);
                o10 = silu_f(o10); o11 = silu_f(o11);
            }
            sm[r0 * SA_ST + 128 + c0]     = o00;
            sm[r0 * SA_ST + 128 + c0 + 1] = o01;
            sm[r1 * SA_ST + 128 + c0]     = o10;
            sm[r1 * SA_ST + 128 + c0 + 1] = o11;
        }
    }
    __syncthreads();

    // writeout: row-coalesced scatter-add (edge) or store (node)
    {
        int r = tid >> 2, q = tid & 3;                 // 64 rows x 4 quarters
        const float4* src = (const float4*)&sm[r * SA_ST + 128 + q * 32];
        if (EDGE) {
            int rc = ((int*)sm)[REC_F + r];
            if (rc >= 0) {
                float* dst = &g_aggr[(size_t)rc * HDIM + q * 32];
#pragma unroll
                for (int j = 0; j < 8; j++) {
                    float4 v = src[j];
                    red4(dst + j * 4, v.x, v.y, v.z, v.w);
                }
            }
        } else {
            int gn = m0 + r;
            if (gn < M) {
                float4* dst = (float4*)&out[(size_t)gn * HDIM + q * 32];
#pragma unroll
                for (int j = 0; j < 8; j++) dst[j] = src[j];
            }
        }
    }
}

// ------------------------- launch -------------------------
extern "C" void kernel_launch(void* const* d_in, const int* in_sizes, int n_in,
                              void* d_out, int out_size) {
    const float* x   = (const float*)d_in[0];
    const float* pos = (const float*)d_in[1];
    const int*   ei  = (const int*)d_in[2];
    const float* mw1 = (const float*)d_in[3];
    const float* mb1 = (const float*)d_in[4];
    const float* mw2 = (const float*)d_in[5];
    const float* mb2 = (const float*)d_in[6];
    const float* uw1 = (const float*)d_in[7];
    const float* ub1 = (const float*)d_in[8];
    const float* uw2 = (const float*)d_in[9];
    const float* ub2 = (const float*)d_in[10];

    int N = in_sizes[0] / HDIM;
    int E = in_sizes[2] / 2;

    cudaFuncSetAttribute(mlp_mma_kernel<true>,
                         cudaFuncAttributeMaxDynamicSharedMemorySize, SMEM_BYTES);
    cudaFuncSetAttribute(mlp_mma_kernel<false>,
                         cudaFuncAttributeMaxDynamicSharedMemorySize, SMEM_BYTES);

    zero_kernel<<<256, 256>>>(N * HDIM);
    prep_kernel<<<512, 256>>>(ei, pos, N, E);
    wt_kernel<<<192, 256>>>(mw1, mw2);
    mlp_mma_kernel<true><<<(E + TM - 1) / TM, 256, SMEM_BYTES>>>(
        x, mw1, mb1, mb2, nullptr, E);
    wt_kernel<<<192, 256>>>(uw1, uw2);
    mlp_mma_kernel<false><<<(N + TM - 1) / TM, 256, SMEM_BYTES>>>(
        x, uw1, ub1, ub2, (float*)d_out, N);
}